// round 12
// baseline (speedup 1.0000x reference)
#include <cuda_runtime.h>
#include <math.h>

#define BB 4
#define SS 2048
#define DD 512
#define HH 8
#define DH 64
#define MM (BB*SS)
#define PAD 68   // smem row stride (floats): %4==0 for float4 alignment, shifts banks

// -------- scratch (device globals; allocation-free per harness rules) --------
__device__ float g_XP[MM*DD];
__device__ float g_XM[MM*DD];
__device__ float g_Q [MM*DD];
__device__ float g_K [MM*DD];
__device__ float g_V [MM*DD];
__device__ float g_AT[MM*DD];

// ---- XLA:CPU GenerateVF32Exp replica: classic Cephes structure (two-constant
// ln2 reduction + straight Horner) WITH LLVM fast-math FMA contraction.
// Ladder so far: libdevice .112 / Eigen-new-FMA .130 / CR .030 / classic-noFMA
// .0099 -> structure is classic; this round fuses the contractible roundings.
__device__ __forceinline__ float xla_expf(float x)
{
    const float LOG2EF = 1.44269504088896341f;
    const float C1 = 0.693359375f;          // ln2 high (10-bit mantissa)
    const float C2 = -2.12194440e-4f;       // ln2 low
    const float p0 = 1.9875691500E-4f, p1 = 1.3981999507E-3f,
                p2 = 8.3334519073E-3f, p3 = 4.1665795894E-2f,
                p4 = 1.6666665459E-1f, p5 = 5.0000001201E-1f;

    float fx = floorf(__fmaf_rn(x, LOG2EF, 0.5f));   // contracted mul+add
    float xr = __fmaf_rn(fx, -C1, x);                // x - fx*C1 (product exact)
    xr = __fmaf_rn(fx, -C2, xr);                     // contracted: single rounding
    float zz = __fmul_rn(xr, xr);
    float y = p0;
    y = __fmaf_rn(y, xr, p1);                        // Horner, contracted
    y = __fmaf_rn(y, xr, p2);
    y = __fmaf_rn(y, xr, p3);
    y = __fmaf_rn(y, xr, p4);
    y = __fmaf_rn(y, xr, p5);
    y = __fmaf_rn(y, zz, xr);                        // y*z + x, contracted
    y = __fadd_rn(y, 1.0f);
    int n = (int)fx;                                 // 2^m via exponent build (exact)
    float pow2n = __int_as_float((n + 127) << 23);
    return __fmul_rn(y, pow2n);
}

// -------- kernel 1: positional encoding add --------
// div_term must bit-match the reference's fp32 exp (XLA:CPU vectorized exp).
// sin/cos: only OUTPUT accuracy matters on the same argument bits (1 ulp =
// 1e-7, harmless) -> double sin/cos with full argument reduction.
__global__ void addpe_kernel(const float* __restrict__ mp, const float* __restrict__ mm)
{
    int idx = blockIdx.x * 256 + threadIdx.x;   // over S*D
    if (idx >= SS*DD) return;
    int s = idx >> 9;          // seq position
    int d = idx & (DD-1);      // model dim
    const float C = (float)(9.210340371976184 / 512.0);  // fl32(log(1e4)/512)
    float arg = (float)(d & ~1) * C;             // fp32 multiply (exact-op semantics)
    float dv  = xla_expf(arg);                   // reference-matching expf bits
    float x   = (float)s * dv;                   // fp32 multiply, matches reference
    float pe = (d & 1) ? (float)cos((double)x) : (float)sin((double)x);
#pragma unroll
    for (int b = 0; b < BB; ++b) {
        size_t o = (size_t)b * (SS*DD) + idx;
        g_XP[o] = mp[o] + pe;
        g_XM[o] = mm[o] + pe;
    }
}

// -------- kernel 2: C[M,512] = alpha * A[M,512] @ W[512,512]^T  (torch Linear) --------
// 128x128 tile, BK=8, 256 threads, 8x8 per thread, float4 global loads, reg prefetch.
__global__ __launch_bounds__(256) void sgemm_nt(const float* __restrict__ A,
                                                const float* __restrict__ W,
                                                float* __restrict__ C, float alpha)
{
    __shared__ float As[8][128];
    __shared__ float Bs[8][128];
    const int tid = threadIdx.x;
    const int m0 = blockIdx.y * 128;
    const int n0 = blockIdx.x * 128;
    const int lr = tid >> 1;            // 0..127 (row within tile for loads)
    const int lc = (tid & 1) * 4;       // 0 or 4 (k offset for loads)
    const int tx = tid & 15, ty = tid >> 4;

    const float* Ap = A + (size_t)(m0 + lr) * DD + lc;
    const float* Wp = W + (size_t)(n0 + lr) * DD + lc;

    float acc[8][8];
#pragma unroll
    for (int i = 0; i < 8; ++i)
#pragma unroll
        for (int j = 0; j < 8; ++j) acc[i][j] = 0.f;

    float4 av = *(const float4*)Ap;      // prefetch tile 0
    float4 wv = *(const float4*)Wp;

    for (int k0 = 0; k0 < DD; k0 += 8) {
        __syncthreads();
        As[lc+0][lr] = av.x; As[lc+1][lr] = av.y; As[lc+2][lr] = av.z; As[lc+3][lr] = av.w;
        Bs[lc+0][lr] = wv.x; Bs[lc+1][lr] = wv.y; Bs[lc+2][lr] = wv.z; Bs[lc+3][lr] = wv.w;
        __syncthreads();
        if (k0 + 8 < DD) {               // prefetch next tile while computing
            av = *(const float4*)(Ap + k0 + 8);
            wv = *(const float4*)(Wp + k0 + 8);
        }
#pragma unroll
        for (int k = 0; k < 8; ++k) {
            float a[8], b[8];
            *(float4*)(a)   = *(const float4*)&As[k][ty*8];
            *(float4*)(a+4) = *(const float4*)&As[k][ty*8+4];
            *(float4*)(b)   = *(const float4*)&Bs[k][tx*8];
            *(float4*)(b+4) = *(const float4*)&Bs[k][tx*8+4];
#pragma unroll
            for (int i = 0; i < 8; ++i)
#pragma unroll
                for (int j = 0; j < 8; ++j)
                    acc[i][j] += a[i] * b[j];
        }
    }

    float* Cp = C + (size_t)(m0 + ty*8) * DD + n0 + tx*8;
#pragma unroll
    for (int i = 0; i < 8; ++i) {
        float4 r0 = make_float4(alpha*acc[i][0], alpha*acc[i][1], alpha*acc[i][2], alpha*acc[i][3]);
        float4 r1 = make_float4(alpha*acc[i][4], alpha*acc[i][5], alpha*acc[i][6], alpha*acc[i][7]);
        *(float4*)(Cp + (size_t)i*DD)     = r0;
        *(float4*)(Cp + (size_t)i*DD + 4) = r1;
    }
}

// -------- kernel 3: flash attention, one block = 64 q-rows of one (b,h) --------
// Q pre-scaled by 1/sqrt(dh) (fused into Q GEMM alpha; *0.125 is exact).
__global__ __launch_bounds__(256) void attn_kernel(float* __restrict__ Out)
{
    extern __shared__ float smem[];
    float* Qs = smem;                // [64][PAD]  Qs[d][r]   (dh-major)
    float* Ks = Qs + 64*PAD;         // [64][PAD]  Ks[d][c]
    float* Vs = Ks + 64*PAD;         // [64][PAD]  Vs[c][d]
    float* Ps = Vs + 64*PAD;         // [64][PAD]  Ps[c][r]

    const int bh = blockIdx.y;               // 0..31
    const int b = bh >> 3, h = bh & 7;
    const int q0 = blockIdx.x * 64;
    const int tx = threadIdx.x, ty = threadIdx.y;
    const int tid = ty * 16 + tx;

    const float* Qg = g_Q + (size_t)b * SS * DD + h * DH;
    const float* Kg = g_K + (size_t)b * SS * DD + h * DH;
    const float* Vg = g_V + (size_t)b * SS * DD + h * DH;

#pragma unroll
    for (int it = 0; it < 16; ++it) {
        int idx = it * 256 + tid;
        int r = idx >> 6, d = idx & 63;
        Qs[d*PAD + r] = Qg[(size_t)(q0 + r) * DD + d];
    }

    float m_i[4], l_i[4], o[4][4];
#pragma unroll
    for (int i = 0; i < 4; ++i) {
        m_i[i] = -1e30f; l_i[i] = 0.f;
#pragma unroll
        for (int j = 0; j < 4; ++j) o[i][j] = 0.f;
    }

    for (int t = 0; t < 32; ++t) {
        __syncthreads();                       // prev P@V done before overwriting tiles
        const int c0 = t * 64;
#pragma unroll
        for (int it = 0; it < 16; ++it) {
            int idx = it * 256 + tid;
            int c = idx >> 6, d = idx & 63;
            float kv = Kg[(size_t)(c0 + c) * DD + d];
            float vv = Vg[(size_t)(c0 + c) * DD + d];
            Ks[d*PAD + c] = kv;
            Vs[c*PAD + d] = vv;
        }
        __syncthreads();

        // S = Q K^T  (64x64), thread owns rows ty*4.., cols tx*4..
        float sc[4][4];
#pragma unroll
        for (int i = 0; i < 4; ++i)
#pragma unroll
            for (int j = 0; j < 4; ++j) sc[i][j] = 0.f;
#pragma unroll 8
        for (int d = 0; d < 64; ++d) {
            float4 qa = *(const float4*)&Qs[d*PAD + ty*4];
            float4 kb = *(const float4*)&Ks[d*PAD + tx*4];
            float a[4] = {qa.x, qa.y, qa.z, qa.w};
            float bv[4] = {kb.x, kb.y, kb.z, kb.w};
#pragma unroll
            for (int i = 0; i < 4; ++i)
#pragma unroll
                for (int j = 0; j < 4; ++j)
                    sc[i][j] += a[i] * bv[j];
        }

        // online softmax; row groups are the 16 tx lanes of a half-warp
#pragma unroll
        for (int i = 0; i < 4; ++i) {
            float mx = fmaxf(fmaxf(sc[i][0], sc[i][1]), fmaxf(sc[i][2], sc[i][3]));
#pragma unroll
            for (int off = 8; off > 0; off >>= 1)
                mx = fmaxf(mx, __shfl_xor_sync(0xffffffffu, mx, off));
            float mnew = fmaxf(m_i[i], mx);
            float corr = __expf(m_i[i] - mnew);
            float p0 = __expf(sc[i][0] - mnew);
            float p1 = __expf(sc[i][1] - mnew);
            float p2 = __expf(sc[i][2] - mnew);
            float p3 = __expf(sc[i][3] - mnew);
            float rs = (p0 + p1) + (p2 + p3);
#pragma unroll
            for (int off = 8; off > 0; off >>= 1)
                rs += __shfl_xor_sync(0xffffffffu, rs, off);
            l_i[i] = l_i[i] * corr + rs;
            m_i[i] = mnew;
#pragma unroll
            for (int j = 0; j < 4; ++j) o[i][j] *= corr;
            Ps[(tx*4+0)*PAD + ty*4+i] = p0;
            Ps[(tx*4+1)*PAD + ty*4+i] = p1;
            Ps[(tx*4+2)*PAD + ty*4+i] = p2;
            Ps[(tx*4+3)*PAD + ty*4+i] = p3;
        }
        __syncthreads();

        // O += P V   (64x64 @ 64x64), same 4x4 mapping (rows ty*4, dh cols tx*4)
#pragma unroll 8
        for (int c = 0; c < 64; ++c) {
            float4 pa = *(const float4*)&Ps[c*PAD + ty*4];
            float4 vb = *(const float4*)&Vs[c*PAD + tx*4];
            float p[4] = {pa.x, pa.y, pa.z, pa.w};
            float v[4] = {vb.x, vb.y, vb.z, vb.w};
#pragma unroll
            for (int i = 0; i < 4; ++i)
#pragma unroll
                for (int j = 0; j < 4; ++j)
                    o[i][j] += p[i] * v[j];
        }
    }

    float* Og = Out + ((size_t)b * SS + q0) * DD + h * DH;
#pragma unroll
    for (int i = 0; i < 4; ++i) {
        float inv = 1.0f / l_i[i];
        float4 r = make_float4(o[i][0]*inv, o[i][1]*inv, o[i][2]*inv, o[i][3]*inv);
        *(float4*)&Og[(size_t)(ty*4 + i) * DD + tx*4] = r;
    }
}

// -------- launch --------
extern "C" void kernel_launch(void* const* d_in, const int* in_sizes, int n_in,
                              void* d_out, int out_size)
{
    const float* mp = (const float*)d_in[0];
    const float* mm = (const float*)d_in[1];
    const float* Wq = (const float*)d_in[2];
    const float* Wk = (const float*)d_in[3];
    const float* Wv = (const float*)d_in[4];
    const float* Wo = (const float*)d_in[5];
    float* out = (float*)d_out;

    float *XP, *XM, *Q, *K, *V, *AT;
    cudaGetSymbolAddress((void**)&XP, g_XP);
    cudaGetSymbolAddress((void**)&XM, g_XM);
    cudaGetSymbolAddress((void**)&Q,  g_Q);
    cudaGetSymbolAddress((void**)&K,  g_K);
    cudaGetSymbolAddress((void**)&V,  g_V);
    cudaGetSymbolAddress((void**)&AT, g_AT);

    const int attn_smem = 4 * 64 * PAD * (int)sizeof(float);   // 69632 B
    cudaFuncSetAttribute(attn_kernel, cudaFuncAttributeMaxDynamicSharedMemorySize, attn_smem);

    addpe_kernel<<<(SS*DD + 255) / 256, 256>>>(mp, mm);

    dim3 gg(DD/128, MM/128);   // (4, 64)
    sgemm_nt<<<gg, 256>>>(XP, Wq, Q, 0.125f);   // 1/sqrt(64) fused into Q
    sgemm_nt<<<gg, 256>>>(XM, Wk, K, 1.0f);
    sgemm_nt<<<gg, 256>>>(XM, Wv, V, 1.0f);

    attn_kernel<<<dim3(SS/64, BB*HH), dim3(16, 16), attn_smem>>>(AT);

    sgemm_nt<<<gg, 256>>>(AT, Wo, out, 1.0f);
}

// round 14
// speedup vs baseline: 1.0948x; 1.0948x over previous
#include <cuda_runtime.h>
#include <math.h>
#include <stdint.h>

#define BB 4
#define SS 2048
#define DD 512
#define HH 8
#define DH 64
#define MM (BB*SS)
#define PAD 68   // attn smem row stride

// -------- scratch (device globals; allocation-free per harness rules) --------
__device__ float g_XP[MM*DD];
__device__ float g_XM[MM*DD];
__device__ float g_Q [MM*DD];
__device__ float g_K [MM*DD];
__device__ float g_V [MM*DD];
__device__ float g_AT[MM*DD];

// ======================= mma.sync TF32 helpers (plain sm_100-safe PTX) =======================
__device__ __forceinline__ uint32_t f32_tf32(float x){
    uint32_t r; asm("cvt.rna.tf32.f32 %0, %1;" : "=r"(r) : "f"(x)); return r;
}
#define MMA_TF32(dreg, a, b0_, b1_) \
    asm volatile("mma.sync.aligned.m16n8k8.row.col.f32.tf32.tf32.f32 " \
                 "{%0,%1,%2,%3}, {%4,%5,%6,%7}, {%8,%9}, {%0,%1,%2,%3};" \
                 : "+f"((dreg)[0]), "+f"((dreg)[1]), "+f"((dreg)[2]), "+f"((dreg)[3]) \
                 : "r"((a)[0]), "r"((a)[1]), "r"((a)[2]), "r"((a)[3]), \
                   "r"(b0_), "r"(b1_))

// ======================= exp replica (correctness-critical, unchanged) =======================
__device__ __forceinline__ float xla_expf(float x)
{
    const float LOG2EF = 1.44269504088896341f;
    const float C1 = 0.693359375f;
    const float C2 = -2.12194440e-4f;
    const float p0 = 1.9875691500E-4f, p1 = 1.3981999507E-3f,
                p2 = 8.3334519073E-3f, p3 = 4.1665795894E-2f,
                p4 = 1.6666665459E-1f, p5 = 5.0000001201E-1f;
    float fx = floorf(__fmaf_rn(x, LOG2EF, 0.5f));
    float xr = __fmaf_rn(fx, -C1, x);
    xr = __fmaf_rn(fx, -C2, xr);
    float zz = __fmul_rn(xr, xr);
    float y = p0;
    y = __fmaf_rn(y, xr, p1);
    y = __fmaf_rn(y, xr, p2);
    y = __fmaf_rn(y, xr, p3);
    y = __fmaf_rn(y, xr, p4);
    y = __fmaf_rn(y, xr, p5);
    y = __fmaf_rn(y, zz, xr);
    y = __fadd_rn(y, 1.0f);
    int n = (int)fx;
    float pow2n = __int_as_float((n + 127) << 23);
    return __fmul_rn(y, pow2n);
}

__global__ void addpe_kernel(const float* __restrict__ mp, const float* __restrict__ mm)
{
    int idx = blockIdx.x * 256 + threadIdx.x;
    if (idx >= SS*DD) return;
    int s = idx >> 9;
    int d = idx & (DD-1);
    const float C = (float)(9.210340371976184 / 512.0);
    float arg = (float)(d & ~1) * C;
    float dv  = xla_expf(arg);
    float x   = (float)s * dv;
    float pe = (d & 1) ? (float)cos((double)x) : (float)sin((double)x);
#pragma unroll
    for (int b = 0; b < BB; ++b) {
        size_t o = (size_t)b * (SS*DD) + idx;
        g_XP[o] = mp[o] + pe;
        g_XM[o] = mm[o] + pe;
    }
}

// ======================= mma.sync TF32 GEMM: C = alpha * A @ W^T =======================
// 128x128 tile/CTA, 8 warps (4M x 2N), warp tile 32x64 (2x8 m16n8k8 frags).
// 3xTF32 hi/lo split for fp32-grade accuracy. K in 16 chunks of 32, double-
// buffered smem; stride-36 u32 rows -> conflict-free fragment gathers.
#define STR 36
#define S_AHI 0
#define S_ALO 4608
#define S_WHI 9216
#define S_WLO 13824
#define S_BUF 18432
#define MMAG_SMEM (2 * S_BUF * 4)   // 147456 B

__device__ __forceinline__ void cvt_store(uint32_t* hi, uint32_t* lo,
                                          int row, int half, const float4* v)
{
#pragma unroll
    for (int i = 0; i < 4; ++i) {
        float4 x = v[i];
        uint4 h, l;
        h.x = f32_tf32(x.x); l.x = f32_tf32(x.x - __uint_as_float(h.x));
        h.y = f32_tf32(x.y); l.y = f32_tf32(x.y - __uint_as_float(h.y));
        h.z = f32_tf32(x.z); l.z = f32_tf32(x.z - __uint_as_float(h.z));
        h.w = f32_tf32(x.w); l.w = f32_tf32(x.w - __uint_as_float(h.w));
        int col = half * 16 + i * 4;
        *(uint4*)(hi + row * STR + col) = h;
        *(uint4*)(lo + row * STR + col) = l;
    }
}

__global__ __launch_bounds__(256, 1) void mma_gemm(const float* __restrict__ A,
                                                   const float* __restrict__ W,
                                                   float* __restrict__ C, float alpha)
{
    extern __shared__ uint32_t smu[];
    const int tid = threadIdx.x;
    const int m0 = blockIdx.y * 128;
    const int n0 = blockIdx.x * 128;
    const int wid = tid >> 5, lane = tid & 31;
    const int wm = wid & 3, wn = wid >> 2;       // 4 M-warps x 2 N-warps
    const int g = lane >> 2, t = lane & 3;

    const int row = tid >> 1, half = tid & 1;    // staging: one half-row (16 floats)
    const float4* Ap4 = (const float4*)(A + (size_t)(m0 + row) * DD);
    const float4* Wp4 = (const float4*)(W + (size_t)(n0 + row) * DD);

    float d[2][8][4];
#pragma unroll
    for (int m = 0; m < 2; ++m)
#pragma unroll
        for (int j = 0; j < 8; ++j)
#pragma unroll
            for (int k = 0; k < 4; ++k) d[m][j][k] = 0.f;

    float4 pa[4], pw[4];
#pragma unroll
    for (int i = 0; i < 4; ++i) { pa[i] = Ap4[half*4 + i]; pw[i] = Wp4[half*4 + i]; }
    cvt_store(smu + S_AHI, smu + S_ALO, row, half, pa);
    cvt_store(smu + S_WHI, smu + S_WLO, row, half, pw);
    __syncthreads();

    for (int c = 0; c < 16; ++c) {
        uint32_t* sb = smu + (c & 1) * S_BUF;
        if (c < 15) {                             // prefetch next chunk into regs
#pragma unroll
            for (int i = 0; i < 4; ++i) {
                pa[i] = Ap4[(c+1)*8 + half*4 + i];
                pw[i] = Wp4[(c+1)*8 + half*4 + i];
            }
        }
#pragma unroll
        for (int k0 = 0; k0 < 32; k0 += 8) {
            uint32_t ah[2][4], al[2][4];
#pragma unroll
            for (int m = 0; m < 2; ++m) {
                int r1 = (wm*32 + m*16 + g) * STR + k0 + t;
                ah[m][0] = sb[S_AHI + r1];           ah[m][1] = sb[S_AHI + r1 + 8*STR];
                ah[m][2] = sb[S_AHI + r1 + 4];       ah[m][3] = sb[S_AHI + r1 + 8*STR + 4];
                al[m][0] = sb[S_ALO + r1];           al[m][1] = sb[S_ALO + r1 + 8*STR];
                al[m][2] = sb[S_ALO + r1 + 4];       al[m][3] = sb[S_ALO + r1 + 8*STR + 4];
            }
#pragma unroll
            for (int j = 0; j < 8; ++j) {
                int rb = (wn*64 + j*8 + g) * STR + k0 + t;
                uint32_t bh0 = sb[S_WHI + rb], bh1 = sb[S_WHI + rb + 4];
                uint32_t bl0 = sb[S_WLO + rb], bl1 = sb[S_WLO + rb + 4];
#pragma unroll
                for (int m = 0; m < 2; ++m) {
                    MMA_TF32(d[m][j], ah[m], bh0, bh1);   // hi*hi
                    MMA_TF32(d[m][j], ah[m], bl0, bl1);   // hi*lo
                    MMA_TF32(d[m][j], al[m], bh0, bh1);   // lo*hi
                }
            }
        }
        if (c < 15) {
            uint32_t* nb = smu + ((c+1) & 1) * S_BUF;
            cvt_store(nb + S_AHI, nb + S_ALO, row, half, pa);
            cvt_store(nb + S_WHI, nb + S_WLO, row, half, pw);
        }
        __syncthreads();
    }

    // epilogue: d[m][j]{0,1}=row g cols 2t,2t+1 ; {2,3}=row g+8
#pragma unroll
    for (int m = 0; m < 2; ++m) {
        int r1 = m0 + wm*32 + m*16 + g;
#pragma unroll
        for (int j = 0; j < 8; ++j) {
            int cb = n0 + wn*64 + j*8 + 2*t;
            float2 lo = make_float2(alpha * d[m][j][0], alpha * d[m][j][1]);
            float2 hi = make_float2(alpha * d[m][j][2], alpha * d[m][j][3]);
            *(float2*)(C + (size_t)r1       * DD + cb) = lo;
            *(float2*)(C + (size_t)(r1 + 8) * DD + cb) = hi;
        }
    }
}

// ======================= flash attention (unchanged SIMT; mma.sync next round) ==============
__global__ __launch_bounds__(256) void attn_kernel(float* __restrict__ Out)
{
    extern __shared__ float smem[];
    float* Qs = smem;
    float* Ks = Qs + 64*PAD;
    float* Vs = Ks + 64*PAD;
    float* Ps = Vs + 64*PAD;

    const int bh = blockIdx.y;
    const int b = bh >> 3, h = bh & 7;
    const int q0 = blockIdx.x * 64;
    const int tx = threadIdx.x, ty = threadIdx.y;
    const int tid = ty * 16 + tx;

    const float* Qg = g_Q + (size_t)b * SS * DD + h * DH;
    const float* Kg = g_K + (size_t)b * SS * DD + h * DH;
    const float* Vg = g_V + (size_t)b * SS * DD + h * DH;

#pragma unroll
    for (int it = 0; it < 16; ++it) {
        int idx = it * 256 + tid;
        int r = idx >> 6, d = idx & 63;
        Qs[d*PAD + r] = Qg[(size_t)(q0 + r) * DD + d];
    }

    float m_i[4], l_i[4], o[4][4];
#pragma unroll
    for (int i = 0; i < 4; ++i) {
        m_i[i] = -1e30f; l_i[i] = 0.f;
#pragma unroll
        for (int j = 0; j < 4; ++j) o[i][j] = 0.f;
    }

    for (int t = 0; t < 32; ++t) {
        __syncthreads();
        const int c0 = t * 64;
#pragma unroll
        for (int it = 0; it < 16; ++it) {
            int idx = it * 256 + tid;
            int c = idx >> 6, d = idx & 63;
            float kv = Kg[(size_t)(c0 + c) * DD + d];
            float vv = Vg[(size_t)(c0 + c) * DD + d];
            Ks[d*PAD + c] = kv;
            Vs[c*PAD + d] = vv;
        }
        __syncthreads();

        float sc[4][4];
#pragma unroll
        for (int i = 0; i < 4; ++i)
#pragma unroll
            for (int j = 0; j < 4; ++j) sc[i][j] = 0.f;
#pragma unroll 8
        for (int d = 0; d < 64; ++d) {
            float4 qa = *(const float4*)&Qs[d*PAD + ty*4];
            float4 kb = *(const float4*)&Ks[d*PAD + tx*4];
            float a[4] = {qa.x, qa.y, qa.z, qa.w};
            float bv[4] = {kb.x, kb.y, kb.z, kb.w};
#pragma unroll
            for (int i = 0; i < 4; ++i)
#pragma unroll
                for (int j = 0; j < 4; ++j)
                    sc[i][j] += a[i] * bv[j];
        }

#pragma unroll
        for (int i = 0; i < 4; ++i) {
            float mx = fmaxf(fmaxf(sc[i][0], sc[i][1]), fmaxf(sc[i][2], sc[i][3]));
#pragma unroll
            for (int off = 8; off > 0; off >>= 1)
                mx = fmaxf(mx, __shfl_xor_sync(0xffffffffu, mx, off));
            float mnew = fmaxf(m_i[i], mx);
            float corr = __expf(m_i[i] - mnew);
            float p0 = __expf(sc[i][0] - mnew);
            float p1 = __expf(sc[i][1] - mnew);
            float p2 = __expf(sc[i][2] - mnew);
            float p3 = __expf(sc[i][3] - mnew);
            float rs = (p0 + p1) + (p2 + p3);
#pragma unroll
            for (int off = 8; off > 0; off >>= 1)
                rs += __shfl_xor_sync(0xffffffffu, rs, off);
            l_i[i] = l_i[i] * corr + rs;
            m_i[i] = mnew;
#pragma unroll
            for (int j = 0; j < 4; ++j) o[i][j] *= corr;
            Ps[(tx*4+0)*PAD + ty*4+i] = p0;
            Ps[(tx*4+1)*PAD + ty*4+i] = p1;
            Ps[(tx*4+2)*PAD + ty*4+i] = p2;
            Ps[(tx*4+3)*PAD + ty*4+i] = p3;
        }
        __syncthreads();

#pragma unroll 8
        for (int c = 0; c < 64; ++c) {
            float4 pa = *(const float4*)&Ps[c*PAD + ty*4];
            float4 vb = *(const float4*)&Vs[c*PAD + tx*4];
            float p[4] = {pa.x, pa.y, pa.z, pa.w};
            float v[4] = {vb.x, vb.y, vb.z, vb.w};
#pragma unroll
            for (int i = 0; i < 4; ++i)
#pragma unroll
                for (int j = 0; j < 4; ++j)
                    o[i][j] += p[i] * v[j];
        }
    }

    float* Og = Out + ((size_t)b * SS + q0) * DD + h * DH;
#pragma unroll
    for (int i = 0; i < 4; ++i) {
        float inv = 1.0f / l_i[i];
        float4 r = make_float4(o[i][0]*inv, o[i][1]*inv, o[i][2]*inv, o[i][3]*inv);
        *(float4*)&Og[(size_t)(ty*4 + i) * DD + tx*4] = r;
    }
}

// ======================= launch =======================
extern "C" void kernel_launch(void* const* d_in, const int* in_sizes, int n_in,
                              void* d_out, int out_size)
{
    const float* mp = (const float*)d_in[0];
    const float* mm = (const float*)d_in[1];
    const float* Wq = (const float*)d_in[2];
    const float* Wk = (const float*)d_in[3];
    const float* Wv = (const float*)d_in[4];
    const float* Wo = (const float*)d_in[5];
    float* out = (float*)d_out;

    float *XP, *XM, *Q, *K, *V, *AT;
    cudaGetSymbolAddress((void**)&XP, g_XP);
    cudaGetSymbolAddress((void**)&XM, g_XM);
    cudaGetSymbolAddress((void**)&Q,  g_Q);
    cudaGetSymbolAddress((void**)&K,  g_K);
    cudaGetSymbolAddress((void**)&V,  g_V);
    cudaGetSymbolAddress((void**)&AT, g_AT);

    const int attn_smem = 4 * 64 * PAD * (int)sizeof(float);   // 69632 B
    cudaFuncSetAttribute(attn_kernel, cudaFuncAttributeMaxDynamicSharedMemorySize, attn_smem);
    cudaFuncSetAttribute(mma_gemm, cudaFuncAttributeMaxDynamicSharedMemorySize, MMAG_SMEM);

    addpe_kernel<<<(SS*DD + 255) / 256, 256>>>(mp, mm);

    dim3 gg(DD/128, MM/128);   // (4, 64)
    mma_gemm<<<gg, 256, MMAG_SMEM>>>(XP, Wq, Q, 0.125f);   // 1/sqrt(64) fused into Q
    mma_gemm<<<gg, 256, MMAG_SMEM>>>(XM, Wk, K, 1.0f);
    mma_gemm<<<gg, 256, MMAG_SMEM>>>(XM, Wv, V, 1.0f);

    attn_kernel<<<dim3(SS/64, BB*HH), dim3(16, 16), attn_smem>>>(AT);

    mma_gemm<<<gg, 256, MMAG_SMEM>>>(AT, Wo, out, 1.0f);
}

// round 15
// speedup vs baseline: 1.0953x; 1.0005x over previous
#include <cuda_runtime.h>
#include <math.h>
#include <stdint.h>

#define BB 4
#define SS 2048
#define DD 512
#define HH 8
#define DH 64
#define MM (BB*SS)
#define PAD 68   // attn smem row stride

// -------- scratch (device globals; allocation-free per harness rules) --------
__device__ float g_XP[MM*DD];
__device__ float g_XM[MM*DD];
__device__ float g_Q [MM*DD];
__device__ float g_K [MM*DD];
__device__ float g_V [MM*DD];
__device__ float g_AT[MM*DD];

// ======================= mma.sync TF32 helpers (plain sm_100-safe PTX) =======================
__device__ __forceinline__ uint32_t f32_tf32(float x){
    uint32_t r; asm("cvt.rna.tf32.f32 %0, %1;" : "=r"(r) : "f"(x)); return r;
}
#define MMA_TF32(dreg, a, b0_, b1_) \
    asm volatile("mma.sync.aligned.m16n8k8.row.col.f32.tf32.tf32.f32 " \
                 "{%0,%1,%2,%3}, {%4,%5,%6,%7}, {%8,%9}, {%0,%1,%2,%3};" \
                 : "+f"((dreg)[0]), "+f"((dreg)[1]), "+f"((dreg)[2]), "+f"((dreg)[3]) \
                 : "r"((a)[0]), "r"((a)[1]), "r"((a)[2]), "r"((a)[3]), \
                   "r"(b0_), "r"(b1_))

// ======================= exp replica (correctness-critical, unchanged) =======================
__device__ __forceinline__ float xla_expf(float x)
{
    const float LOG2EF = 1.44269504088896341f;
    const float C1 = 0.693359375f;
    const float C2 = -2.12194440e-4f;
    const float p0 = 1.9875691500E-4f, p1 = 1.3981999507E-3f,
                p2 = 8.3334519073E-3f, p3 = 4.1665795894E-2f,
                p4 = 1.6666665459E-1f, p5 = 5.0000001201E-1f;
    float fx = floorf(__fmaf_rn(x, LOG2EF, 0.5f));
    float xr = __fmaf_rn(fx, -C1, x);
    xr = __fmaf_rn(fx, -C2, xr);
    float zz = __fmul_rn(xr, xr);
    float y = p0;
    y = __fmaf_rn(y, xr, p1);
    y = __fmaf_rn(y, xr, p2);
    y = __fmaf_rn(y, xr, p3);
    y = __fmaf_rn(y, xr, p4);
    y = __fmaf_rn(y, xr, p5);
    y = __fmaf_rn(y, zz, xr);
    y = __fadd_rn(y, 1.0f);
    int n = (int)fx;
    float pow2n = __int_as_float((n + 127) << 23);
    return __fmul_rn(y, pow2n);
}

__global__ void addpe_kernel(const float* __restrict__ mp, const float* __restrict__ mm)
{
    int idx = blockIdx.x * 256 + threadIdx.x;
    if (idx >= SS*DD) return;
    int s = idx >> 9;
    int d = idx & (DD-1);
    const float C = (float)(9.210340371976184 / 512.0);
    float arg = (float)(d & ~1) * C;
    float dv  = xla_expf(arg);
    float x   = (float)s * dv;
    float pe = (d & 1) ? (float)cos((double)x) : (float)sin((double)x);
#pragma unroll
    for (int b = 0; b < BB; ++b) {
        size_t o = (size_t)b * (SS*DD) + idx;
        g_XP[o] = mp[o] + pe;
        g_XM[o] = mm[o] + pe;
    }
}

// ======================= mma.sync TF32 GEMM: C = alpha * A @ W^T =======================
// 128x128 tile/CTA, 8 warps (4M x 2N), warp tile 32x64 (2x8 m16n8k8 frags).
// 3xTF32 hi/lo split for fp32-grade accuracy. K in 16 chunks of 32, double-
// buffered smem; stride-36 u32 rows -> conflict-free fragment gathers.
#define STR 36
#define S_AHI 0
#define S_ALO 4608
#define S_WHI 9216
#define S_WLO 13824
#define S_BUF 18432
#define MMAG_SMEM (2 * S_BUF * 4)   // 147456 B

__device__ __forceinline__ void cvt_store(uint32_t* hi, uint32_t* lo,
                                          int row, int half, const float4* v)
{
#pragma unroll
    for (int i = 0; i < 4; ++i) {
        float4 x = v[i];
        uint4 h, l;
        h.x = f32_tf32(x.x); l.x = f32_tf32(x.x - __uint_as_float(h.x));
        h.y = f32_tf32(x.y); l.y = f32_tf32(x.y - __uint_as_float(h.y));
        h.z = f32_tf32(x.z); l.z = f32_tf32(x.z - __uint_as_float(h.z));
        h.w = f32_tf32(x.w); l.w = f32_tf32(x.w - __uint_as_float(h.w));
        int col = half * 16 + i * 4;
        *(uint4*)(hi + row * STR + col) = h;
        *(uint4*)(lo + row * STR + col) = l;
    }
}

__global__ __launch_bounds__(256, 1) void mma_gemm(const float* __restrict__ A,
                                                   const float* __restrict__ W,
                                                   float* __restrict__ C, float alpha)
{
    extern __shared__ uint32_t smu[];
    const int tid = threadIdx.x;
    const int m0 = blockIdx.y * 128;
    const int n0 = blockIdx.x * 128;
    const int wid = tid >> 5, lane = tid & 31;
    const int wm = wid & 3, wn = wid >> 2;       // 4 M-warps x 2 N-warps
    const int g = lane >> 2, t = lane & 3;

    const int row = tid >> 1, half = tid & 1;    // staging: one half-row (16 floats)
    const float4* Ap4 = (const float4*)(A + (size_t)(m0 + row) * DD);
    const float4* Wp4 = (const float4*)(W + (size_t)(n0 + row) * DD);

    float d[2][8][4];
#pragma unroll
    for (int m = 0; m < 2; ++m)
#pragma unroll
        for (int j = 0; j < 8; ++j)
#pragma unroll
            for (int k = 0; k < 4; ++k) d[m][j][k] = 0.f;

    float4 pa[4], pw[4];
#pragma unroll
    for (int i = 0; i < 4; ++i) { pa[i] = Ap4[half*4 + i]; pw[i] = Wp4[half*4 + i]; }
    cvt_store(smu + S_AHI, smu + S_ALO, row, half, pa);
    cvt_store(smu + S_WHI, smu + S_WLO, row, half, pw);
    __syncthreads();

    for (int c = 0; c < 16; ++c) {
        uint32_t* sb = smu + (c & 1) * S_BUF;
        if (c < 15) {                             // prefetch next chunk into regs
#pragma unroll
            for (int i = 0; i < 4; ++i) {
                pa[i] = Ap4[(c+1)*8 + half*4 + i];
                pw[i] = Wp4[(c+1)*8 + half*4 + i];
            }
        }
#pragma unroll
        for (int k0 = 0; k0 < 32; k0 += 8) {
            uint32_t ah[2][4], al[2][4];
#pragma unroll
            for (int m = 0; m < 2; ++m) {
                int r1 = (wm*32 + m*16 + g) * STR + k0 + t;
                ah[m][0] = sb[S_AHI + r1];           ah[m][1] = sb[S_AHI + r1 + 8*STR];
                ah[m][2] = sb[S_AHI + r1 + 4];       ah[m][3] = sb[S_AHI + r1 + 8*STR + 4];
                al[m][0] = sb[S_ALO + r1];           al[m][1] = sb[S_ALO + r1 + 8*STR];
                al[m][2] = sb[S_ALO + r1 + 4];       al[m][3] = sb[S_ALO + r1 + 8*STR + 4];
            }
#pragma unroll
            for (int j = 0; j < 8; ++j) {
                int rb = (wn*64 + j*8 + g) * STR + k0 + t;
                uint32_t bh0 = sb[S_WHI + rb], bh1 = sb[S_WHI + rb + 4];
                uint32_t bl0 = sb[S_WLO + rb], bl1 = sb[S_WLO + rb + 4];
#pragma unroll
                for (int m = 0; m < 2; ++m) {
                    MMA_TF32(d[m][j], ah[m], bh0, bh1);   // hi*hi
                    MMA_TF32(d[m][j], ah[m], bl0, bl1);   // hi*lo
                    MMA_TF32(d[m][j], al[m], bh0, bh1);   // lo*hi
                }
            }
        }
        if (c < 15) {
            uint32_t* nb = smu + ((c+1) & 1) * S_BUF;
            cvt_store(nb + S_AHI, nb + S_ALO, row, half, pa);
            cvt_store(nb + S_WHI, nb + S_WLO, row, half, pw);
        }
        __syncthreads();
    }

    // epilogue: d[m][j]{0,1}=row g cols 2t,2t+1 ; {2,3}=row g+8
#pragma unroll
    for (int m = 0; m < 2; ++m) {
        int r1 = m0 + wm*32 + m*16 + g;
#pragma unroll
        for (int j = 0; j < 8; ++j) {
            int cb = n0 + wn*64 + j*8 + 2*t;
            float2 lo = make_float2(alpha * d[m][j][0], alpha * d[m][j][1]);
            float2 hi = make_float2(alpha * d[m][j][2], alpha * d[m][j][3]);
            *(float2*)(C + (size_t)r1       * DD + cb) = lo;
            *(float2*)(C + (size_t)(r1 + 8) * DD + cb) = hi;
        }
    }
}

// ======================= flash attention (unchanged SIMT; mma.sync next round) ==============
__global__ __launch_bounds__(256) void attn_kernel(float* __restrict__ Out)
{
    extern __shared__ float smem[];
    float* Qs = smem;
    float* Ks = Qs + 64*PAD;
    float* Vs = Ks + 64*PAD;
    float* Ps = Vs + 64*PAD;

    const int bh = blockIdx.y;
    const int b = bh >> 3, h = bh & 7;
    const int q0 = blockIdx.x * 64;
    const int tx = threadIdx.x, ty = threadIdx.y;
    const int tid = ty * 16 + tx;

    const float* Qg = g_Q + (size_t)b * SS * DD + h * DH;
    const float* Kg = g_K + (size_t)b * SS * DD + h * DH;
    const float* Vg = g_V + (size_t)b * SS * DD + h * DH;

#pragma unroll
    for (int it = 0; it < 16; ++it) {
        int idx = it * 256 + tid;
        int r = idx >> 6, d = idx & 63;
        Qs[d*PAD + r] = Qg[(size_t)(q0 + r) * DD + d];
    }

    float m_i[4], l_i[4], o[4][4];
#pragma unroll
    for (int i = 0; i < 4; ++i) {
        m_i[i] = -1e30f; l_i[i] = 0.f;
#pragma unroll
        for (int j = 0; j < 4; ++j) o[i][j] = 0.f;
    }

    for (int t = 0; t < 32; ++t) {
        __syncthreads();
        const int c0 = t * 64;
#pragma unroll
        for (int it = 0; it < 16; ++it) {
            int idx = it * 256 + tid;
            int c = idx >> 6, d = idx & 63;
            float kv = Kg[(size_t)(c0 + c) * DD + d];
            float vv = Vg[(size_t)(c0 + c) * DD + d];
            Ks[d*PAD + c] = kv;
            Vs[c*PAD + d] = vv;
        }
        __syncthreads();

        float sc[4][4];
#pragma unroll
        for (int i = 0; i < 4; ++i)
#pragma unroll
            for (int j = 0; j < 4; ++j) sc[i][j] = 0.f;
#pragma unroll 8
        for (int d = 0; d < 64; ++d) {
            float4 qa = *(const float4*)&Qs[d*PAD + ty*4];
            float4 kb = *(const float4*)&Ks[d*PAD + tx*4];
            float a[4] = {qa.x, qa.y, qa.z, qa.w};
            float bv[4] = {kb.x, kb.y, kb.z, kb.w};
#pragma unroll
            for (int i = 0; i < 4; ++i)
#pragma unroll
                for (int j = 0; j < 4; ++j)
                    sc[i][j] += a[i] * bv[j];
        }

#pragma unroll
        for (int i = 0; i < 4; ++i) {
            float mx = fmaxf(fmaxf(sc[i][0], sc[i][1]), fmaxf(sc[i][2], sc[i][3]));
#pragma unroll
            for (int off = 8; off > 0; off >>= 1)
                mx = fmaxf(mx, __shfl_xor_sync(0xffffffffu, mx, off));
            float mnew = fmaxf(m_i[i], mx);
            float corr = __expf(m_i[i] - mnew);
            float p0 = __expf(sc[i][0] - mnew);
            float p1 = __expf(sc[i][1] - mnew);
            float p2 = __expf(sc[i][2] - mnew);
            float p3 = __expf(sc[i][3] - mnew);
            float rs = (p0 + p1) + (p2 + p3);
#pragma unroll
            for (int off = 8; off > 0; off >>= 1)
                rs += __shfl_xor_sync(0xffffffffu, rs, off);
            l_i[i] = l_i[i] * corr + rs;
            m_i[i] = mnew;
#pragma unroll
            for (int j = 0; j < 4; ++j) o[i][j] *= corr;
            Ps[(tx*4+0)*PAD + ty*4+i] = p0;
            Ps[(tx*4+1)*PAD + ty*4+i] = p1;
            Ps[(tx*4+2)*PAD + ty*4+i] = p2;
            Ps[(tx*4+3)*PAD + ty*4+i] = p3;
        }
        __syncthreads();

#pragma unroll 8
        for (int c = 0; c < 64; ++c) {
            float4 pa = *(const float4*)&Ps[c*PAD + ty*4];
            float4 vb = *(const float4*)&Vs[c*PAD + tx*4];
            float p[4] = {pa.x, pa.y, pa.z, pa.w};
            float v[4] = {vb.x, vb.y, vb.z, vb.w};
#pragma unroll
            for (int i = 0; i < 4; ++i)
#pragma unroll
                for (int j = 0; j < 4; ++j)
                    o[i][j] += p[i] * v[j];
        }
    }

    float* Og = Out + ((size_t)b * SS + q0) * DD + h * DH;
#pragma unroll
    for (int i = 0; i < 4; ++i) {
        float inv = 1.0f / l_i[i];
        float4 r = make_float4(o[i][0]*inv, o[i][1]*inv, o[i][2]*inv, o[i][3]*inv);
        *(float4*)&Og[(size_t)(ty*4 + i) * DD + tx*4] = r;
    }
}

// ======================= launch =======================
extern "C" void kernel_launch(void* const* d_in, const int* in_sizes, int n_in,
                              void* d_out, int out_size)
{
    const float* mp = (const float*)d_in[0];
    const float* mm = (const float*)d_in[1];
    const float* Wq = (const float*)d_in[2];
    const float* Wk = (const float*)d_in[3];
    const float* Wv = (const float*)d_in[4];
    const float* Wo = (const float*)d_in[5];
    float* out = (float*)d_out;

    float *XP, *XM, *Q, *K, *V, *AT;
    cudaGetSymbolAddress((void**)&XP, g_XP);
    cudaGetSymbolAddress((void**)&XM, g_XM);
    cudaGetSymbolAddress((void**)&Q,  g_Q);
    cudaGetSymbolAddress((void**)&K,  g_K);
    cudaGetSymbolAddress((void**)&V,  g_V);
    cudaGetSymbolAddress((void**)&AT, g_AT);

    const int attn_smem = 4 * 64 * PAD * (int)sizeof(float);   // 69632 B
    cudaFuncSetAttribute(attn_kernel, cudaFuncAttributeMaxDynamicSharedMemorySize, attn_smem);
    cudaFuncSetAttribute(mma_gemm, cudaFuncAttributeMaxDynamicSharedMemorySize, MMAG_SMEM);

    addpe_kernel<<<(SS*DD + 255) / 256, 256>>>(mp, mm);

    dim3 gg(DD/128, MM/128);   // (4, 64)
    mma_gemm<<<gg, 256, MMAG_SMEM>>>(XP, Wq, Q, 0.125f);   // 1/sqrt(64) fused into Q
    mma_gemm<<<gg, 256, MMAG_SMEM>>>(XM, Wk, K, 1.0f);
    mma_gemm<<<gg, 256, MMAG_SMEM>>>(XM, Wv, V, 1.0f);

    attn_kernel<<<dim3(SS/64, BB*HH), dim3(16, 16), attn_smem>>>(AT);

    mma_gemm<<<gg, 256, MMAG_SMEM>>>(AT, Wo, out, 1.0f);
}

// round 16
// speedup vs baseline: 1.0967x; 1.0013x over previous
#include <cuda_runtime.h>
#include <math.h>
#include <stdint.h>

#define BB 4
#define SS 2048
#define DD 512
#define HH 8
#define DH 64
#define MM (BB*SS)
#define PAD 68   // attn smem row stride

// -------- scratch (device globals; allocation-free per harness rules) --------
__device__ float g_XP[MM*DD];
__device__ float g_XM[MM*DD];
__device__ float g_Q [MM*DD];
__device__ float g_K [MM*DD];
__device__ float g_V [MM*DD];
__device__ float g_AT[MM*DD];

// ======================= mma.sync TF32 helpers (plain sm_100-safe PTX) =======================
__device__ __forceinline__ uint32_t f32_tf32(float x){
    uint32_t r; asm("cvt.rna.tf32.f32 %0, %1;" : "=r"(r) : "f"(x)); return r;
}
#define MMA_TF32(dreg, a, b0_, b1_) \
    asm volatile("mma.sync.aligned.m16n8k8.row.col.f32.tf32.tf32.f32 " \
                 "{%0,%1,%2,%3}, {%4,%5,%6,%7}, {%8,%9}, {%0,%1,%2,%3};" \
                 : "+f"((dreg)[0]), "+f"((dreg)[1]), "+f"((dreg)[2]), "+f"((dreg)[3]) \
                 : "r"((a)[0]), "r"((a)[1]), "r"((a)[2]), "r"((a)[3]), \
                   "r"(b0_), "r"(b1_))

// ======================= exp replica (correctness-critical, unchanged) =======================
__device__ __forceinline__ float xla_expf(float x)
{
    const float LOG2EF = 1.44269504088896341f;
    const float C1 = 0.693359375f;
    const float C2 = -2.12194440e-4f;
    const float p0 = 1.9875691500E-4f, p1 = 1.3981999507E-3f,
                p2 = 8.3334519073E-3f, p3 = 4.1665795894E-2f,
                p4 = 1.6666665459E-1f, p5 = 5.0000001201E-1f;
    float fx = floorf(__fmaf_rn(x, LOG2EF, 0.5f));
    float xr = __fmaf_rn(fx, -C1, x);
    xr = __fmaf_rn(fx, -C2, xr);
    float zz = __fmul_rn(xr, xr);
    float y = p0;
    y = __fmaf_rn(y, xr, p1);
    y = __fmaf_rn(y, xr, p2);
    y = __fmaf_rn(y, xr, p3);
    y = __fmaf_rn(y, xr, p4);
    y = __fmaf_rn(y, xr, p5);
    y = __fmaf_rn(y, zz, xr);
    y = __fadd_rn(y, 1.0f);
    int n = (int)fx;
    float pow2n = __int_as_float((n + 127) << 23);
    return __fmul_rn(y, pow2n);
}

__global__ void addpe_kernel(const float* __restrict__ mp, const float* __restrict__ mm)
{
    int idx = blockIdx.x * 256 + threadIdx.x;
    if (idx >= SS*DD) return;
    int s = idx >> 9;
    int d = idx & (DD-1);
    const float C = (float)(9.210340371976184 / 512.0);
    float arg = (float)(d & ~1) * C;
    float dv  = xla_expf(arg);
    float x   = (float)s * dv;
    float pe = (d & 1) ? (float)cos((double)x) : (float)sin((double)x);
#pragma unroll
    for (int b = 0; b < BB; ++b) {
        size_t o = (size_t)b * (SS*DD) + idx;
        g_XP[o] = mp[o] + pe;
        g_XM[o] = mm[o] + pe;
    }
}

// ======================= mma.sync TF32 GEMM: C = alpha * A @ W^T =======================
// 128x128 tile/CTA, 8 warps (4M x 2N), warp tile 32x64 (2x8 m16n8k8 frags).
// 3xTF32 hi/lo split for fp32-grade accuracy. K in 16 chunks of 32, double-
// buffered smem; stride-36 u32 rows -> conflict-free fragment gathers.
#define STR 36
#define S_AHI 0
#define S_ALO 4608
#define S_WHI 9216
#define S_WLO 13824
#define S_BUF 18432
#define MMAG_SMEM (2 * S_BUF * 4)   // 147456 B

__device__ __forceinline__ void cvt_store(uint32_t* hi, uint32_t* lo,
                                          int row, int half, const float4* v)
{
#pragma unroll
    for (int i = 0; i < 4; ++i) {
        float4 x = v[i];
        uint4 h, l;
        h.x = f32_tf32(x.x); l.x = f32_tf32(x.x - __uint_as_float(h.x));
        h.y = f32_tf32(x.y); l.y = f32_tf32(x.y - __uint_as_float(h.y));
        h.z = f32_tf32(x.z); l.z = f32_tf32(x.z - __uint_as_float(h.z));
        h.w = f32_tf32(x.w); l.w = f32_tf32(x.w - __uint_as_float(h.w));
        int col = half * 16 + i * 4;
        *(uint4*)(hi + row * STR + col) = h;
        *(uint4*)(lo + row * STR + col) = l;
    }
}

__global__ __launch_bounds__(256, 1) void mma_gemm(const float* __restrict__ A,
                                                   const float* __restrict__ W,
                                                   float* __restrict__ C, float alpha)
{
    extern __shared__ uint32_t smu[];
    const int tid = threadIdx.x;
    const int m0 = blockIdx.y * 128;
    const int n0 = blockIdx.x * 128;
    const int wid = tid >> 5, lane = tid & 31;
    const int wm = wid & 3, wn = wid >> 2;       // 4 M-warps x 2 N-warps
    const int g = lane >> 2, t = lane & 3;

    const int row = tid >> 1, half = tid & 1;    // staging: one half-row (16 floats)
    const float4* Ap4 = (const float4*)(A + (size_t)(m0 + row) * DD);
    const float4* Wp4 = (const float4*)(W + (size_t)(n0 + row) * DD);

    float d[2][8][4];
#pragma unroll
    for (int m = 0; m < 2; ++m)
#pragma unroll
        for (int j = 0; j < 8; ++j)
#pragma unroll
            for (int k = 0; k < 4; ++k) d[m][j][k] = 0.f;

    float4 pa[4], pw[4];
#pragma unroll
    for (int i = 0; i < 4; ++i) { pa[i] = Ap4[half*4 + i]; pw[i] = Wp4[half*4 + i]; }
    cvt_store(smu + S_AHI, smu + S_ALO, row, half, pa);
    cvt_store(smu + S_WHI, smu + S_WLO, row, half, pw);
    __syncthreads();

    for (int c = 0; c < 16; ++c) {
        uint32_t* sb = smu + (c & 1) * S_BUF;
        if (c < 15) {                             // prefetch next chunk into regs
#pragma unroll
            for (int i = 0; i < 4; ++i) {
                pa[i] = Ap4[(c+1)*8 + half*4 + i];
                pw[i] = Wp4[(c+1)*8 + half*4 + i];
            }
        }
#pragma unroll
        for (int k0 = 0; k0 < 32; k0 += 8) {
            uint32_t ah[2][4], al[2][4];
#pragma unroll
            for (int m = 0; m < 2; ++m) {
                int r1 = (wm*32 + m*16 + g) * STR + k0 + t;
                ah[m][0] = sb[S_AHI + r1];           ah[m][1] = sb[S_AHI + r1 + 8*STR];
                ah[m][2] = sb[S_AHI + r1 + 4];       ah[m][3] = sb[S_AHI + r1 + 8*STR + 4];
                al[m][0] = sb[S_ALO + r1];           al[m][1] = sb[S_ALO + r1 + 8*STR];
                al[m][2] = sb[S_ALO + r1 + 4];       al[m][3] = sb[S_ALO + r1 + 8*STR + 4];
            }
#pragma unroll
            for (int j = 0; j < 8; ++j) {
                int rb = (wn*64 + j*8 + g) * STR + k0 + t;
                uint32_t bh0 = sb[S_WHI + rb], bh1 = sb[S_WHI + rb + 4];
                uint32_t bl0 = sb[S_WLO + rb], bl1 = sb[S_WLO + rb + 4];
#pragma unroll
                for (int m = 0; m < 2; ++m) {
                    MMA_TF32(d[m][j], ah[m], bh0, bh1);   // hi*hi
                    MMA_TF32(d[m][j], ah[m], bl0, bl1);   // hi*lo
                    MMA_TF32(d[m][j], al[m], bh0, bh1);   // lo*hi
                }
            }
        }
        if (c < 15) {
            uint32_t* nb = smu + ((c+1) & 1) * S_BUF;
            cvt_store(nb + S_AHI, nb + S_ALO, row, half, pa);
            cvt_store(nb + S_WHI, nb + S_WLO, row, half, pw);
        }
        __syncthreads();
    }

    // epilogue: d[m][j]{0,1}=row g cols 2t,2t+1 ; {2,3}=row g+8
#pragma unroll
    for (int m = 0; m < 2; ++m) {
        int r1 = m0 + wm*32 + m*16 + g;
#pragma unroll
        for (int j = 0; j < 8; ++j) {
            int cb = n0 + wn*64 + j*8 + 2*t;
            float2 lo = make_float2(alpha * d[m][j][0], alpha * d[m][j][1]);
            float2 hi = make_float2(alpha * d[m][j][2], alpha * d[m][j][3]);
            *(float2*)(C + (size_t)r1       * DD + cb) = lo;
            *(float2*)(C + (size_t)(r1 + 8) * DD + cb) = hi;
        }
    }
}

// ======================= flash attention (unchanged SIMT; mma.sync next round) ==============
__global__ __launch_bounds__(256) void attn_kernel(float* __restrict__ Out)
{
    extern __shared__ float smem[];
    float* Qs = smem;
    float* Ks = Qs + 64*PAD;
    float* Vs = Ks + 64*PAD;
    float* Ps = Vs + 64*PAD;

    const int bh = blockIdx.y;
    const int b = bh >> 3, h = bh & 7;
    const int q0 = blockIdx.x * 64;
    const int tx = threadIdx.x, ty = threadIdx.y;
    const int tid = ty * 16 + tx;

    const float* Qg = g_Q + (size_t)b * SS * DD + h * DH;
    const float* Kg = g_K + (size_t)b * SS * DD + h * DH;
    const float* Vg = g_V + (size_t)b * SS * DD + h * DH;

#pragma unroll
    for (int it = 0; it < 16; ++it) {
        int idx = it * 256 + tid;
        int r = idx >> 6, d = idx & 63;
        Qs[d*PAD + r] = Qg[(size_t)(q0 + r) * DD + d];
    }

    float m_i[4], l_i[4], o[4][4];
#pragma unroll
    for (int i = 0; i < 4; ++i) {
        m_i[i] = -1e30f; l_i[i] = 0.f;
#pragma unroll
        for (int j = 0; j < 4; ++j) o[i][j] = 0.f;
    }

    for (int t = 0; t < 32; ++t) {
        __syncthreads();
        const int c0 = t * 64;
#pragma unroll
        for (int it = 0; it < 16; ++it) {
            int idx = it * 256 + tid;
            int c = idx >> 6, d = idx & 63;
            float kv = Kg[(size_t)(c0 + c) * DD + d];
            float vv = Vg[(size_t)(c0 + c) * DD + d];
            Ks[d*PAD + c] = kv;
            Vs[c*PAD + d] = vv;
        }
        __syncthreads();

        float sc[4][4];
#pragma unroll
        for (int i = 0; i < 4; ++i)
#pragma unroll
            for (int j = 0; j < 4; ++j) sc[i][j] = 0.f;
#pragma unroll 8
        for (int d = 0; d < 64; ++d) {
            float4 qa = *(const float4*)&Qs[d*PAD + ty*4];
            float4 kb = *(const float4*)&Ks[d*PAD + tx*4];
            float a[4] = {qa.x, qa.y, qa.z, qa.w};
            float bv[4] = {kb.x, kb.y, kb.z, kb.w};
#pragma unroll
            for (int i = 0; i < 4; ++i)
#pragma unroll
                for (int j = 0; j < 4; ++j)
                    sc[i][j] += a[i] * bv[j];
        }

#pragma unroll
        for (int i = 0; i < 4; ++i) {
            float mx = fmaxf(fmaxf(sc[i][0], sc[i][1]), fmaxf(sc[i][2], sc[i][3]));
#pragma unroll
            for (int off = 8; off > 0; off >>= 1)
                mx = fmaxf(mx, __shfl_xor_sync(0xffffffffu, mx, off));
            float mnew = fmaxf(m_i[i], mx);
            float corr = __expf(m_i[i] - mnew);
            float p0 = __expf(sc[i][0] - mnew);
            float p1 = __expf(sc[i][1] - mnew);
            float p2 = __expf(sc[i][2] - mnew);
            float p3 = __expf(sc[i][3] - mnew);
            float rs = (p0 + p1) + (p2 + p3);
#pragma unroll
            for (int off = 8; off > 0; off >>= 1)
                rs += __shfl_xor_sync(0xffffffffu, rs, off);
            l_i[i] = l_i[i] * corr + rs;
            m_i[i] = mnew;
#pragma unroll
            for (int j = 0; j < 4; ++j) o[i][j] *= corr;
            Ps[(tx*4+0)*PAD + ty*4+i] = p0;
            Ps[(tx*4+1)*PAD + ty*4+i] = p1;
            Ps[(tx*4+2)*PAD + ty*4+i] = p2;
            Ps[(tx*4+3)*PAD + ty*4+i] = p3;
        }
        __syncthreads();

#pragma unroll 8
        for (int c = 0; c < 64; ++c) {
            float4 pa = *(const float4*)&Ps[c*PAD + ty*4];
            float4 vb = *(const float4*)&Vs[c*PAD + tx*4];
            float p[4] = {pa.x, pa.y, pa.z, pa.w};
            float v[4] = {vb.x, vb.y, vb.z, vb.w};
#pragma unroll
            for (int i = 0; i < 4; ++i)
#pragma unroll
                for (int j = 0; j < 4; ++j)
                    o[i][j] += p[i] * v[j];
        }
    }

    float* Og = Out + ((size_t)b * SS + q0) * DD + h * DH;
#pragma unroll
    for (int i = 0; i < 4; ++i) {
        float inv = 1.0f / l_i[i];
        float4 r = make_float4(o[i][0]*inv, o[i][1]*inv, o[i][2]*inv, o[i][3]*inv);
        *(float4*)&Og[(size_t)(ty*4 + i) * DD + tx*4] = r;
    }
}

// ======================= launch =======================
extern "C" void kernel_launch(void* const* d_in, const int* in_sizes, int n_in,
                              void* d_out, int out_size)
{
    const float* mp = (const float*)d_in[0];
    const float* mm = (const float*)d_in[1];
    const float* Wq = (const float*)d_in[2];
    const float* Wk = (const float*)d_in[3];
    const float* Wv = (const float*)d_in[4];
    const float* Wo = (const float*)d_in[5];
    float* out = (float*)d_out;

    float *XP, *XM, *Q, *K, *V, *AT;
    cudaGetSymbolAddress((void**)&XP, g_XP);
    cudaGetSymbolAddress((void**)&XM, g_XM);
    cudaGetSymbolAddress((void**)&Q,  g_Q);
    cudaGetSymbolAddress((void**)&K,  g_K);
    cudaGetSymbolAddress((void**)&V,  g_V);
    cudaGetSymbolAddress((void**)&AT, g_AT);

    const int attn_smem = 4 * 64 * PAD * (int)sizeof(float);   // 69632 B
    cudaFuncSetAttribute(attn_kernel, cudaFuncAttributeMaxDynamicSharedMemorySize, attn_smem);
    cudaFuncSetAttribute(mma_gemm, cudaFuncAttributeMaxDynamicSharedMemorySize, MMAG_SMEM);

    addpe_kernel<<<(SS*DD + 255) / 256, 256>>>(mp, mm);

    dim3 gg(DD/128, MM/128);   // (4, 64)
    mma_gemm<<<gg, 256, MMAG_SMEM>>>(XP, Wq, Q, 0.125f);   // 1/sqrt(64) fused into Q
    mma_gemm<<<gg, 256, MMAG_SMEM>>>(XM, Wk, K, 1.0f);
    mma_gemm<<<gg, 256, MMAG_SMEM>>>(XM, Wv, V, 1.0f);

    attn_kernel<<<dim3(SS/64, BB*HH), dim3(16, 16), attn_smem>>>(AT);

    mma_gemm<<<gg, 256, MMAG_SMEM>>>(AT, Wo, out, 1.0f);
}